// round 4
// baseline (speedup 1.0000x reference)
#include <cuda_runtime.h>
#include <cuda_bf16.h>
#include <cstdint>

// Shapes:
//   node_emb:    [65536, 64] f32   (d_in[0])
//   feature_emb: [512, 64]   f32   (d_in[1])
//   W:           [1, 128]    f32   (d_in[2])  (w_node = W[0:64], w_feat = W[64:128])
//   b:           [1]         f32   (d_in[3])
//   out[i,j] = node_emb[i,:].w_node + feature_emb[j,:].w_feat + b

#define BS 65536
#define NF 512
#define D  64
#define ROWS_PER_WARP 4

// Scratch (allocation-free rule: __device__ globals). 256KB + 2KB, L2-resident.
__device__ float g_node[BS];
__device__ float g_feat[NF];

// ---------------------------------------------------------------------------
// Kernel 1: both projections, warp-per-row.
//   warps [0, NF)        -> g_feat[w]   = feature_emb[w,:]  . W[64:128] + b
//   warps [NF, NF+BS)    -> g_node[w-NF]= node_emb[w-NF,:]  . W[0:64]
// Read-bound: 16.1 MB. Fully coalesced float2 per lane + butterfly reduce.
// ---------------------------------------------------------------------------
__global__ __launch_bounds__(256) void proj_kernel(
    const float* __restrict__ node_emb,
    const float* __restrict__ feature_emb,
    const float* __restrict__ W,
    const float* __restrict__ b)
{
    const int warp = (blockIdx.x * 256 + threadIdx.x) >> 5;
    const int lane = threadIdx.x & 31;

    float2 v, w;
    if (warp < NF) {
        v = reinterpret_cast<const float2*>(feature_emb)[warp * 32 + lane];
        w = reinterpret_cast<const float2*>(W)[32 + lane];     // W[64 + 2*lane ..]
    } else {
        const int row = warp - NF;
        v = reinterpret_cast<const float2*>(node_emb)[row * 32 + lane];
        w = reinterpret_cast<const float2*>(W)[lane];          // W[2*lane ..]
    }
    float p = fmaf(v.x, w.x, v.y * w.y);

    #pragma unroll
    for (int off = 16; off > 0; off >>= 1)
        p += __shfl_xor_sync(0xffffffffu, p, off);

    if (lane == 0) {
        if (warp < NF) g_feat[warp] = p + b[0];
        else           g_node[warp - NF] = p;
    }
}

// ---------------------------------------------------------------------------
// Kernel 2: pure store streamer. Warp handles 4 rows.
// Per warp: 1x LDG.128 of node_proj (L2 hit), 4x LDG.128 of g_feat (L1 hit),
// then 16 independent STG.128, each writing 512 contiguous bytes per warp.
// __stcs keeps the 128MB output stream from evicting g_feat/g_node.
// ---------------------------------------------------------------------------
__global__ __launch_bounds__(256) void stream_kernel(float* __restrict__ out)
{
    const int warp = (blockIdx.x * 256 + threadIdx.x) >> 5;
    const int lane = threadIdx.x & 31;
    const int row0 = warp * ROWS_PER_WARP;

    // 4 node projections for this warp's rows (uniform address -> 1 sector).
    const float4 pn = *reinterpret_cast<const float4*>(g_node + row0);

    // Per-lane feat values, interleaved so each STG.128 covers 512B contiguous.
    const float4* f4 = reinterpret_cast<const float4*>(g_feat);
    const float4 f0 = f4[      lane];
    const float4 f1 = f4[ 32 + lane];
    const float4 f2 = f4[ 64 + lane];
    const float4 f3 = f4[ 96 + lane];

    float4* o4 = reinterpret_cast<float4*>(out + (size_t)row0 * NF);

    #pragma unroll
    for (int r = 0; r < ROWS_PER_WARP; r++) {
        const float p = (r == 0) ? pn.x : (r == 1) ? pn.y : (r == 2) ? pn.z : pn.w;
        float4* row = o4 + r * (NF / 4);
        float4 t;
        t.x = f0.x + p; t.y = f0.y + p; t.z = f0.z + p; t.w = f0.w + p;
        __stcs(row +      lane, t);
        t.x = f1.x + p; t.y = f1.y + p; t.z = f1.z + p; t.w = f1.w + p;
        __stcs(row + 32 + lane, t);
        t.x = f2.x + p; t.y = f2.y + p; t.z = f2.z + p; t.w = f2.w + p;
        __stcs(row + 64 + lane, t);
        t.x = f3.x + p; t.y = f3.y + p; t.z = f3.z + p; t.w = f3.w + p;
        __stcs(row + 96 + lane, t);
    }
}

// ---------------------------------------------------------------------------
extern "C" void kernel_launch(void* const* d_in, const int* in_sizes, int n_in,
                              void* d_out, int out_size)
{
    const float* node_emb    = (const float*)d_in[0];
    const float* feature_emb = (const float*)d_in[1];
    const float* W           = (const float*)d_in[2];
    const float* b           = (const float*)d_in[3];
    float*       out         = (float*)d_out;

    // Kernel 1: (NF + BS) warps = 66048 -> 8256 blocks x 256 threads.
    proj_kernel<<<(NF + BS) / 8, 256>>>(node_emb, feature_emb, W, b);

    // Kernel 2: 65536/4 = 16384 warps -> 2048 blocks x 256 threads.
    stream_kernel<<<BS / (8 * ROWS_PER_WARP), 256>>>(out);
}

// round 7
// speedup vs baseline: 1.1523x; 1.1523x over previous
#include <cuda_runtime.h>
#include <cuda_bf16.h>
#include <cstdint>

// Shapes:
//   node_emb:    [65536, 64] f32   (d_in[0])
//   feature_emb: [512, 64]   f32   (d_in[1])
//   W:           [1, 128]    f32   (d_in[2])  (w_node = W[0:64], w_feat = W[64:128])
//   b:           [1]         f32   (d_in[3])
//   out[i,j] = node_emb[i,:].w_node + feature_emb[j,:].w_feat + b

#define BS 65536
#define NF 512
#define D  64
#define ROWS_PER_WARP 4

// feat_proj + b scratch (allocation-free rule: __device__ global; L2/L1-resident, 2KB).
__device__ float g_feat[NF];

// ---------------------------------------------------------------------------
// Kernel 1 (tiny): g_feat[j] = feature_emb[j,:] . W[64:128] + b
// warp-per-row, 512 rows -> 64 blocks x 256 threads.
// ---------------------------------------------------------------------------
__global__ __launch_bounds__(256) void feat_kernel(
    const float* __restrict__ feature_emb,
    const float* __restrict__ W,
    const float* __restrict__ b)
{
    const int warp = (blockIdx.x * 256 + threadIdx.x) >> 5;
    const int lane = threadIdx.x & 31;
    if (warp >= NF) return;

    const float2 v = reinterpret_cast<const float2*>(feature_emb)[warp * 32 + lane];
    const float2 w = reinterpret_cast<const float2*>(W)[32 + lane];  // W[64 + 2*lane ..]
    float p = fmaf(v.x, w.x, v.y * w.y);

    #pragma unroll
    for (int off = 16; off > 0; off >>= 1)
        p += __shfl_xor_sync(0xffffffffu, p, off);

    if (lane == 0)
        g_feat[warp] = p + b[0];
}

// ---------------------------------------------------------------------------
// Kernel 2: fused node_proj + broadcast stream. Warp handles 4 rows.
//  - 4 node-row loads issued up front (independent, MLP=4/warp),
//  - 4 independent shfl-reduce chains interleaved stage-by-stage,
//  - 16 independent STG.128, each writing 512 contiguous bytes per warp.
// The 16MB node read overlaps the 134MB store stream (proved viable at
// 5.93 TB/s combined in round 2).
// ---------------------------------------------------------------------------
__global__ __launch_bounds__(256) void fused_stream_kernel(
    const float* __restrict__ node_emb,
    const float* __restrict__ W,
    float* __restrict__ out)
{
    const int warp = (blockIdx.x * 256 + threadIdx.x) >> 5;
    const int lane = threadIdx.x & 31;
    const int row0 = warp * ROWS_PER_WARP;

    // Prefetch all 4 node rows (fully coalesced float2 per lane, 256B/row/warp).
    const float2* ne = reinterpret_cast<const float2*>(node_emb);
    const float2 v0 = ne[(row0 + 0) * 32 + lane];
    const float2 v1 = ne[(row0 + 1) * 32 + lane];
    const float2 v2 = ne[(row0 + 2) * 32 + lane];
    const float2 v3 = ne[(row0 + 3) * 32 + lane];
    const float2 w  = reinterpret_cast<const float2*>(W)[lane];   // W[2*lane ..]

    // Per-lane feat values, interleaved so each STG.128 covers 512B contiguous.
    const float4* f4 = reinterpret_cast<const float4*>(g_feat);
    const float4 f0 = f4[      lane];
    const float4 f1 = f4[ 32 + lane];
    const float4 f2 = f4[ 64 + lane];
    const float4 f3 = f4[ 96 + lane];

    // 4 independent butterfly reductions, interleaved per stage for ILP.
    float p[ROWS_PER_WARP];
    p[0] = fmaf(v0.x, w.x, v0.y * w.y);
    p[1] = fmaf(v1.x, w.x, v1.y * w.y);
    p[2] = fmaf(v2.x, w.x, v2.y * w.y);
    p[3] = fmaf(v3.x, w.x, v3.y * w.y);
    #pragma unroll
    for (int off = 16; off > 0; off >>= 1) {
        #pragma unroll
        for (int r = 0; r < ROWS_PER_WARP; r++)
            p[r] += __shfl_xor_sync(0xffffffffu, p[r], off);
    }

    float4* o4 = reinterpret_cast<float4*>(out + (size_t)row0 * NF);

    #pragma unroll
    for (int r = 0; r < ROWS_PER_WARP; r++) {
        const float pr = p[r];
        float4* row = o4 + r * (NF / 4);
        float4 t;
        t.x = f0.x + pr; t.y = f0.y + pr; t.z = f0.z + pr; t.w = f0.w + pr;
        __stcs(row +      lane, t);
        t.x = f1.x + pr; t.y = f1.y + pr; t.z = f1.z + pr; t.w = f1.w + pr;
        __stcs(row + 32 + lane, t);
        t.x = f2.x + pr; t.y = f2.y + pr; t.z = f2.z + pr; t.w = f2.w + pr;
        __stcs(row + 64 + lane, t);
        t.x = f3.x + pr; t.y = f3.y + pr; t.z = f3.z + pr; t.w = f3.w + pr;
        __stcs(row + 96 + lane, t);
    }
}

// ---------------------------------------------------------------------------
extern "C" void kernel_launch(void* const* d_in, const int* in_sizes, int n_in,
                              void* d_out, int out_size)
{
    const float* node_emb    = (const float*)d_in[0];
    const float* feature_emb = (const float*)d_in[1];
    const float* W           = (const float*)d_in[2];
    const float* b           = (const float*)d_in[3];
    float*       out         = (float*)d_out;

    // Kernel 1: 512 warps -> 64 blocks x 256 threads (~1.3us).
    feat_kernel<<<64, 256>>>(feature_emb, W, b);

    // Kernel 2: 65536/4 = 16384 warps -> 2048 blocks x 256 threads.
    fused_stream_kernel<<<BS / (8 * ROWS_PER_WARP), 256>>>(node_emb, W, out);
}

// round 10
// speedup vs baseline: 1.1550x; 1.0024x over previous
#include <cuda_runtime.h>
#include <cuda_bf16.h>
#include <cstdint>

// Shapes:
//   node_emb:    [65536, 64] f32   (d_in[0])
//   feature_emb: [512, 64]   f32   (d_in[1])
//   W:           [1, 128]    f32   (d_in[2])  (w_node = W[0:64], w_feat = W[64:128])
//   b:           [1]         f32   (d_in[3])
//   out[i,j] = node_emb[i,:].w_node + feature_emb[j,:].w_feat + b

#define BS 65536
#define NF 512
#define D  64
#define ROWS_PER_WARP 4

// feat_proj + b scratch (allocation-free rule: __device__ global; L2/L1-resident, 2KB).
__device__ float g_feat[NF];

// ---------------------------------------------------------------------------
// Kernel 1 (tiny): g_feat[j] = feature_emb[j,:] . W[64:128] + b
// warp-per-row, 512 rows -> 64 blocks x 256 threads.
// ---------------------------------------------------------------------------
__global__ __launch_bounds__(256) void feat_kernel(
    const float* __restrict__ feature_emb,
    const float* __restrict__ W,
    const float* __restrict__ b)
{
    const int warp = (blockIdx.x * 256 + threadIdx.x) >> 5;
    const int lane = threadIdx.x & 31;
    if (warp >= NF) return;

    const float2 v = reinterpret_cast<const float2*>(feature_emb)[warp * 32 + lane];
    const float2 w = reinterpret_cast<const float2*>(W)[32 + lane];  // W[64 + 2*lane ..]
    float p = fmaf(v.x, w.x, v.y * w.y);

    #pragma unroll
    for (int off = 16; off > 0; off >>= 1)
        p += __shfl_xor_sync(0xffffffffu, p, off);

    if (lane == 0)
        g_feat[warp] = p + b[0];
}

// ---------------------------------------------------------------------------
// Kernel 2: fused node_proj + broadcast stream, launched with PDL so it
// overlaps feat_kernel. Ordering:
//   1. node-row loads + W load + dot/shfl  (independent of g_feat)
//   2. cudaGridDependencySynchronize()     (waits for feat_kernel grid)
//   3. g_feat loads + 16 independent STG.128
// The sync latency hides behind the node DRAM loads.
// ---------------------------------------------------------------------------
__global__ __launch_bounds__(256) void fused_stream_kernel(
    const float* __restrict__ node_emb,
    const float* __restrict__ W,
    float* __restrict__ out)
{
    const int warp = (blockIdx.x * 256 + threadIdx.x) >> 5;
    const int lane = threadIdx.x & 31;
    const int row0 = warp * ROWS_PER_WARP;

    // Prefetch all 4 node rows (fully coalesced float2 per lane, 256B/row/warp).
    const float2* ne = reinterpret_cast<const float2*>(node_emb);
    const float2 v0 = ne[(row0 + 0) * 32 + lane];
    const float2 v1 = ne[(row0 + 1) * 32 + lane];
    const float2 v2 = ne[(row0 + 2) * 32 + lane];
    const float2 v3 = ne[(row0 + 3) * 32 + lane];
    const float2 w  = reinterpret_cast<const float2*>(W)[lane];   // W[2*lane ..]

    // 4 independent butterfly reductions, interleaved per stage for ILP.
    float p[ROWS_PER_WARP];
    p[0] = fmaf(v0.x, w.x, v0.y * w.y);
    p[1] = fmaf(v1.x, w.x, v1.y * w.y);
    p[2] = fmaf(v2.x, w.x, v2.y * w.y);
    p[3] = fmaf(v3.x, w.x, v3.y * w.y);
    #pragma unroll
    for (int off = 16; off > 0; off >>= 1) {
        #pragma unroll
        for (int r = 0; r < ROWS_PER_WARP; r++)
            p[r] += __shfl_xor_sync(0xffffffffu, p[r], off);
    }

    // PDL: wait for feat_kernel's grid to complete before touching g_feat.
    cudaGridDependencySynchronize();

    // Per-lane feat values, interleaved so each STG.128 covers 512B contiguous.
    const float4* f4 = reinterpret_cast<const float4*>(g_feat);
    const float4 f0 = f4[      lane];
    const float4 f1 = f4[ 32 + lane];
    const float4 f2 = f4[ 64 + lane];
    const float4 f3 = f4[ 96 + lane];

    float4* o4 = reinterpret_cast<float4*>(out + (size_t)row0 * NF);

    #pragma unroll
    for (int r = 0; r < ROWS_PER_WARP; r++) {
        const float pr = p[r];
        float4* row = o4 + r * (NF / 4);
        float4 t;
        t.x = f0.x + pr; t.y = f0.y + pr; t.z = f0.z + pr; t.w = f0.w + pr;
        __stcs(row +      lane, t);
        t.x = f1.x + pr; t.y = f1.y + pr; t.z = f1.z + pr; t.w = f1.w + pr;
        __stcs(row + 32 + lane, t);
        t.x = f2.x + pr; t.y = f2.y + pr; t.z = f2.z + pr; t.w = f2.w + pr;
        __stcs(row + 64 + lane, t);
        t.x = f3.x + pr; t.y = f3.y + pr; t.z = f3.z + pr; t.w = f3.w + pr;
        __stcs(row + 96 + lane, t);
    }
}

// ---------------------------------------------------------------------------
extern "C" void kernel_launch(void* const* d_in, const int* in_sizes, int n_in,
                              void* d_out, int out_size)
{
    const float* node_emb    = (const float*)d_in[0];
    const float* feature_emb = (const float*)d_in[1];
    const float* W           = (const float*)d_in[2];
    const float* b           = (const float*)d_in[3];
    float*       out         = (float*)d_out;

    // Kernel 1: 512 warps -> 64 blocks x 256 threads (~1.1us).
    feat_kernel<<<64, 256>>>(feature_emb, W, b);

    // Kernel 2 with programmatic dependent launch: starts while feat_kernel
    // runs; the in-kernel cudaGridDependencySynchronize() enforces the g_feat
    // dependency. Stream capture turns this into a programmatic graph edge.
    cudaLaunchConfig_t cfg = {};
    cfg.gridDim  = dim3(BS / (8 * ROWS_PER_WARP));   // 2048 blocks
    cfg.blockDim = dim3(256);
    cfg.stream   = 0;
    cudaLaunchAttribute attr[1];
    attr[0].id = cudaLaunchAttributeProgrammaticStreamSerialization;
    attr[0].val.programmaticStreamSerializationAllowed = 1;
    cfg.attrs    = attr;
    cfg.numAttrs = 1;
    cudaLaunchKernelEx(&cfg, fused_stream_kernel, node_emb, W, out);
}